// round 16
// baseline (speedup 1.0000x reference)
#include <cuda_runtime.h>

#define HW   4096
#define NC   128
#define CR   32
#define KK   49

// scratch for generated per-pixel kernels: [B=4][49][64*64]
__device__ float g_kernel[4 * KK * HW];

// ---------------------------------------------------------------------------
// Kernel 1: generate involution kernels.
// 512 blocks x 128 threads. Block = 32 pixels, 4 warp-parts per pixel.
// Vectorized weight staging (8+4 LDG.128/thread). smem 38.5KB -> 5 blocks/SM,
// 20 warps/SM, grid 512 = single wave.
// ---------------------------------------------------------------------------
__global__ __launch_bounds__(128, 5) void gen_kernel(
    const float* __restrict__ x,  const float* __restrict__ w1,
    const float* __restrict__ b1, const float* __restrict__ gamma,
    const float* __restrict__ beta, const float* __restrict__ mean,
    const float* __restrict__ var,  const float* __restrict__ w2,
    const float* __restrict__ b2)
{
    __shared__ __align__(16) float w1t[NC * CR];      // [c][o]  16 KB
    __shared__ __align__(16) float w2tt[52 * CR];     // [t][o]  6.5 KB
    __shared__ __align__(16) float fbuf[4 * CR * 32]; // [part][o][pix] 16 KB
    __shared__ float s_scale[CR], s_shift[CR];

    const int tid = threadIdx.x;

    // ---- vectorized staging ----
    {
        const float4* w1f4 = (const float4*)w1;       // [o][c/4], 1024 float4
        #pragma unroll
        for (int j = 0; j < 8; j++) {
            int idx = tid + j * 128;                  // 0..1023
            float4 w = w1f4[idx];
            int o  = idx >> 5;                        // 0..31
            int cq = idx & 31;                        // c-quad
            w1t[(cq * 4 + 0) * CR + o] = w.x;
            w1t[(cq * 4 + 1) * CR + o] = w.y;
            w1t[(cq * 4 + 2) * CR + o] = w.z;
            w1t[(cq * 4 + 3) * CR + o] = w.w;
        }
        const float4* w2f4 = (const float4*)w2;       // 392 float4
        float4* w2t4 = (float4*)w2tt;
        #pragma unroll
        for (int j = 0; j < 4; j++) {
            int idx = tid + j * 128;                  // 0..511, need 416
            if (idx < 392)       w2t4[idx] = w2f4[idx];
            else if (idx < 416)  w2t4[idx] = make_float4(0.f, 0.f, 0.f, 0.f);
        }
        if (tid < CR) {
            float sc = gamma[tid] * rsqrtf(var[tid] + 1e-5f);
            s_scale[tid] = sc;
            s_shift[tid] = fmaf(b1[tid], sc, beta[tid] - mean[tid] * sc);
        }
    }
    __syncthreads();

    const int pix_l = tid & 31;
    const int part  = tid >> 5;            // warp id 0..3
    const int pixel = blockIdx.x * 32 + pix_l;
    const int b     = pixel >> 12;
    const int hw    = pixel & (HW - 1);

    // ---- stage 1: partial 1x1 conv over this part's 32 channels ----
    float fp[CR];
    #pragma unroll
    for (int o = 0; o < CR; o++) fp[o] = 0.f;

    const float* xp = x + ((size_t)(b * NC + part * 32)) * HW + hw;
    #pragma unroll 8
    for (int c = 0; c < 32; c++) {
        float xv = xp[(size_t)c * HW];
        const float4* wr = (const float4*)&w1t[(part * 32 + c) * CR];
        #pragma unroll
        for (int o4 = 0; o4 < 8; o4++) {
            float4 w = wr[o4];
            fp[o4*4+0] = fmaf(w.x, xv, fp[o4*4+0]);
            fp[o4*4+1] = fmaf(w.y, xv, fp[o4*4+1]);
            fp[o4*4+2] = fmaf(w.z, xv, fp[o4*4+2]);
            fp[o4*4+3] = fmaf(w.w, xv, fp[o4*4+3]);
        }
    }
    {
        float* fb = fbuf + part * (CR * 32) + pix_l;
        #pragma unroll
        for (int o = 0; o < CR; o++) fb[o * 32] = fp[o];
    }
    __syncthreads();

    // ---- stage 2: combine partials + BN + ReLU ----
    float f[CR];
    #pragma unroll
    for (int o = 0; o < CR; o++) {
        float v = fbuf[0*(CR*32) + o*32 + pix_l]
                + fbuf[1*(CR*32) + o*32 + pix_l]
                + fbuf[2*(CR*32) + o*32 + pix_l]
                + fbuf[3*(CR*32) + o*32 + pix_l];
        v = fmaf(v, s_scale[o], s_shift[o]);
        f[o] = fmaxf(v, 0.f);
    }

    // ---- stage 3: this part's 13 kernel outputs ----
    const int t0 = part * 13;
    float* kp = g_kernel + (size_t)b * KK * HW + hw;
    #pragma unroll
    for (int tt = 0; tt < 13; tt++) {
        int t = t0 + tt;
        const float4* wr = (const float4*)&w2tt[t * CR];
        float a0 = 0.f, a1 = 0.f, a2 = 0.f, a3 = 0.f;
        #pragma unroll
        for (int o4 = 0; o4 < 8; o4++) {
            float4 w = wr[o4];
            a0 = fmaf(w.x, f[o4*4+0], a0);
            a1 = fmaf(w.y, f[o4*4+1], a1);
            a2 = fmaf(w.z, f[o4*4+2], a2);
            a3 = fmaf(w.w, f[o4*4+3], a3);
        }
        if (t < KK)
            kp[(size_t)t * HW] = (a0 + a1) + (a2 + a3) + b2[t];
    }
}

// ---------------------------------------------------------------------------
// Kernel 2: involution (R14 winner, unchanged).
// grid 512 = (b, 8 8-row tiles, 16 8-channel groups), 128 threads, one wave.
// 4 px/thread x 8 ch, kv double-buffered float4, 32 FMA chains.
// ---------------------------------------------------------------------------
__global__ __launch_bounds__(128, 4) void inv_kernel(
    const float* __restrict__ x, float* __restrict__ out)
{
    __shared__ __align__(16) float xs[8 * 14 * 72];   // 32256 B

    const int bx = blockIdx.x;              // 0..511
    const int b  = bx >> 7;
    const int ht = (bx >> 4) & 7;           // 8 row-tiles of 8
    const int cg = bx & 15;                 // 16 groups of 8 channels
    const int h0 = ht * 8;
    const int c0 = cg * 8;

    const int tid  = threadIdx.x;
    const int row  = tid >> 4;              // 0..7 output row
    const int wloc = (tid & 15) * 4;        // 0,4,...,60

    // ---- halo main fill: 1792 aligned float4 loads (14 per thread) ----
    #pragma unroll
    for (int it = 0; it < 14; it++) {
        int idx = tid + it * 128;           // 0..1791
        int ch  = idx / 224;                // 14*16 per channel
        int rem = idx - ch * 224;
        int r   = rem >> 4;
        int k   = rem & 15;
        int gr  = h0 - 3 + r;
        float4 v = make_float4(0.f, 0.f, 0.f, 0.f);
        if ((unsigned)gr < 64u)
            v = *(const float4*)(x + ((size_t)(b * NC + c0 + ch) << 12)
                                   + (gr << 6) + (k << 2));
        float* d = xs + ch * 1008 + r * 72 + 3 + (k << 2);
        d[0] = v.x; d[1] = v.y; d[2] = v.z; d[3] = v.w;
    }
    // ---- halo edges: cols 0..2 and 67..71 -> zero (7 per thread) ----
    #pragma unroll
    for (int it = 0; it < 7; it++) {
        int idx = tid + it * 128;           // 0..895
        int ch  = idx / 112;                // 14*8 per channel
        int rem = idx - ch * 112;
        int r   = rem >> 3;
        int e   = rem & 7;
        int col = (e < 3) ? e : (64 + e);   // 0,1,2,67..71
        xs[ch * 1008 + r * 72 + col] = 0.f;
    }

    const float* kpix = g_kernel + (size_t)b * KK * HW + (h0 + row) * 64 + wloc;

    float acc[8][4];
    #pragma unroll
    for (int cc = 0; cc < 8; cc++)
        #pragma unroll
        for (int p = 0; p < 4; p++) acc[cc][p] = 0.f;

    // prefetch kernel tap-row 0 (overlaps halo STS drain)
    float4 kr[7], krn[7];
    #pragma unroll
    for (int j = 0; j < 7; j++)
        kr[j] = *(const float4*)(kpix + (size_t)j * HW);

    __syncthreads();

    #pragma unroll 1
    for (int i = 0; i < 7; i++) {
        // prefetch next tap-row's weights while computing this one
        if (i < 6) {
            #pragma unroll
            for (int j = 0; j < 7; j++)
                krn[j] = *(const float4*)(kpix + (size_t)((i + 1) * 7 + j) * HW);
        }
        const float* xrow = xs + (row + i) * 72 + wloc;
        #pragma unroll
        for (int cc = 0; cc < 8; cc++) {
            const float* rp = xrow + cc * 1008;
            float4 u0 = *(const float4*)(rp);
            float4 u1 = *(const float4*)(rp + 4);
            float2 u2 = *(const float2*)(rp + 8);
            float va[10] = {u0.x,u0.y,u0.z,u0.w, u1.x,u1.y,u1.z,u1.w, u2.x,u2.y};
            float a0 = acc[cc][0], a1 = acc[cc][1], a2 = acc[cc][2], a3 = acc[cc][3];
            #pragma unroll
            for (int j = 0; j < 7; j++) {
                a0 = fmaf(kr[j].x, va[j],     a0);
                a1 = fmaf(kr[j].y, va[j + 1], a1);
                a2 = fmaf(kr[j].z, va[j + 2], a2);
                a3 = fmaf(kr[j].w, va[j + 3], a3);
            }
            acc[cc][0] = a0; acc[cc][1] = a1; acc[cc][2] = a2; acc[cc][3] = a3;
        }
        #pragma unroll
        for (int j = 0; j < 7; j++) kr[j] = krn[j];
    }

    const size_t out_pix = (size_t)(h0 + row) * 64 + wloc;
    #pragma unroll
    for (int cc = 0; cc < 8; cc++) {
        float4 res;
        res.x = acc[cc][0]; res.y = acc[cc][1];
        res.z = acc[cc][2]; res.w = acc[cc][3];
        *(float4*)(out + ((size_t)(b * NC + c0 + cc) << 12) + out_pix) = res;
    }
}

extern "C" void kernel_launch(void* const* d_in, const int* in_sizes, int n_in,
                              void* d_out, int out_size)
{
    const float* x     = (const float*)d_in[0];
    const float* w1    = (const float*)d_in[1];
    const float* b1    = (const float*)d_in[2];
    const float* gamma = (const float*)d_in[3];
    const float* beta  = (const float*)d_in[4];
    const float* mean  = (const float*)d_in[5];
    const float* var   = (const float*)d_in[6];
    const float* w2    = (const float*)d_in[7];
    const float* b2    = (const float*)d_in[8];

    gen_kernel<<<512, 128>>>(x, w1, b1, gamma, beta, mean, var, w2, b2);
    inv_kernel<<<512, 128>>>(x, (float*)d_out);
}

// round 17
// speedup vs baseline: 1.0963x; 1.0963x over previous
#include <cuda_runtime.h>

#define HW   4096
#define NC   128
#define CR   32
#define KK   49

// scratch for generated per-pixel kernels: [B=4][49][64*64]
__device__ float g_kernel[4 * KK * HW];

// ---------------------------------------------------------------------------
// Kernel 1: generate involution kernels.
// 256 blocks x 256 threads (R4 shape). Block = 64 pixels, 4 warp-parts.
// Stage 1 x-loads double-buffered in 16-wide register batches (MLP~16).
// ---------------------------------------------------------------------------
__global__ __launch_bounds__(256, 3) void gen_kernel(
    const float* __restrict__ x,  const float* __restrict__ w1,
    const float* __restrict__ b1, const float* __restrict__ gamma,
    const float* __restrict__ beta, const float* __restrict__ mean,
    const float* __restrict__ var,  const float* __restrict__ w2,
    const float* __restrict__ b2)
{
    __shared__ __align__(16) float w1t[NC * CR];      // [c][o]  16 KB
    __shared__ __align__(16) float w2tt[52 * CR];     // [t][o]  6.5 KB
    __shared__ __align__(16) float fbuf[4 * CR * 64]; // [part][o][pix] 32 KB
    __shared__ float s_scale[CR], s_shift[CR];

    const int tid = threadIdx.x;

    for (int i = tid; i < NC * CR; i += 256) {
        int o = i >> 7, c = i & 127;
        w1t[c * CR + o] = w1[i];
    }
    for (int i = tid; i < 52 * CR; i += 256)
        w2tt[i] = (i < KK * CR) ? w2[i] : 0.f;
    if (tid < CR) {
        float sc = gamma[tid] * rsqrtf(var[tid] + 1e-5f);
        s_scale[tid] = sc;
        s_shift[tid] = fmaf(b1[tid], sc, beta[tid] - mean[tid] * sc);
    }
    __syncthreads();

    const int pix_l = tid & 63;
    const int part  = tid >> 6;            // warp-uniform
    const int pixel = blockIdx.x * 64 + pix_l;
    const int b     = pixel >> 12;
    const int hw    = pixel & (HW - 1);

    // ---- stage 1: partial 1x1 conv, double-buffered 16-wide x batches ----
    float fp[CR];
    #pragma unroll
    for (int o = 0; o < CR; o++) fp[o] = 0.f;

    const float* xp = x + ((size_t)(b * NC + part * 32)) * HW + hw;

    float xva[16], xvb[16];
    #pragma unroll
    for (int c = 0; c < 16; c++) xva[c] = xp[(size_t)c * HW];          // batch 0
    #pragma unroll
    for (int c = 0; c < 16; c++) xvb[c] = xp[(size_t)(16 + c) * HW];   // batch 1

    #pragma unroll
    for (int c = 0; c < 16; c++) {
        float xv = xva[c];
        const float4* wr = (const float4*)&w1t[(part * 32 + c) * CR];
        #pragma unroll
        for (int o4 = 0; o4 < 8; o4++) {
            float4 w = wr[o4];
            fp[o4*4+0] = fmaf(w.x, xv, fp[o4*4+0]);
            fp[o4*4+1] = fmaf(w.y, xv, fp[o4*4+1]);
            fp[o4*4+2] = fmaf(w.z, xv, fp[o4*4+2]);
            fp[o4*4+3] = fmaf(w.w, xv, fp[o4*4+3]);
        }
    }
    #pragma unroll
    for (int c = 0; c < 16; c++) {
        float xv = xvb[c];
        const float4* wr = (const float4*)&w1t[(part * 32 + 16 + c) * CR];
        #pragma unroll
        for (int o4 = 0; o4 < 8; o4++) {
            float4 w = wr[o4];
            fp[o4*4+0] = fmaf(w.x, xv, fp[o4*4+0]);
            fp[o4*4+1] = fmaf(w.y, xv, fp[o4*4+1]);
            fp[o4*4+2] = fmaf(w.z, xv, fp[o4*4+2]);
            fp[o4*4+3] = fmaf(w.w, xv, fp[o4*4+3]);
        }
    }

    {
        float* fb = fbuf + part * (CR * 64) + pix_l;
        #pragma unroll
        for (int o = 0; o < CR; o++) fb[o * 64] = fp[o];
    }
    __syncthreads();

    // ---- stage 2: combine partials + BN + ReLU ----
    float f[CR];
    #pragma unroll
    for (int o = 0; o < CR; o++) {
        float v = fbuf[0*(CR*64) + o*64 + pix_l]
                + fbuf[1*(CR*64) + o*64 + pix_l]
                + fbuf[2*(CR*64) + o*64 + pix_l]
                + fbuf[3*(CR*64) + o*64 + pix_l];
        v = fmaf(v, s_scale[o], s_shift[o]);
        f[o] = fmaxf(v, 0.f);
    }

    // ---- stage 3: this part's 13 kernel outputs ----
    const int t0 = part * 13;
    float* kp = g_kernel + (size_t)b * KK * HW + hw;
    #pragma unroll
    for (int tt = 0; tt < 13; tt++) {
        int t = t0 + tt;
        const float4* wr = (const float4*)&w2tt[t * CR];
        float a0 = 0.f, a1 = 0.f, a2 = 0.f, a3 = 0.f;
        #pragma unroll
        for (int o4 = 0; o4 < 8; o4++) {
            float4 w = wr[o4];
            a0 = fmaf(w.x, f[o4*4+0], a0);
            a1 = fmaf(w.y, f[o4*4+1], a1);
            a2 = fmaf(w.z, f[o4*4+2], a2);
            a3 = fmaf(w.w, f[o4*4+3], a3);
        }
        if (t < KK)
            kp[(size_t)t * HW] = (a0 + a1) + (a2 + a3) + b2[t];
    }
}

// ---------------------------------------------------------------------------
// Kernel 2: involution (R14 winner, unchanged).
// grid 512 = (b, 8 8-row tiles, 16 8-channel groups), 128 threads, one wave.
// 4 px/thread x 8 ch, kv double-buffered float4, 32 FMA chains.
// ---------------------------------------------------------------------------
__global__ __launch_bounds__(128, 4) void inv_kernel(
    const float* __restrict__ x, float* __restrict__ out)
{
    __shared__ __align__(16) float xs[8 * 14 * 72];   // 32256 B

    const int bx = blockIdx.x;              // 0..511
    const int b  = bx >> 7;
    const int ht = (bx >> 4) & 7;           // 8 row-tiles of 8
    const int cg = bx & 15;                 // 16 groups of 8 channels
    const int h0 = ht * 8;
    const int c0 = cg * 8;

    const int tid  = threadIdx.x;
    const int row  = tid >> 4;              // 0..7 output row
    const int wloc = (tid & 15) * 4;        // 0,4,...,60

    // ---- halo main fill: 1792 aligned float4 loads (14 per thread) ----
    #pragma unroll
    for (int it = 0; it < 14; it++) {
        int idx = tid + it * 128;           // 0..1791
        int ch  = idx / 224;                // 14*16 per channel
        int rem = idx - ch * 224;
        int r   = rem >> 4;
        int k   = rem & 15;
        int gr  = h0 - 3 + r;
        float4 v = make_float4(0.f, 0.f, 0.f, 0.f);
        if ((unsigned)gr < 64u)
            v = *(const float4*)(x + ((size_t)(b * NC + c0 + ch) << 12)
                                   + (gr << 6) + (k << 2));
        float* d = xs + ch * 1008 + r * 72 + 3 + (k << 2);
        d[0] = v.x; d[1] = v.y; d[2] = v.z; d[3] = v.w;
    }
    // ---- halo edges: cols 0..2 and 67..71 -> zero (7 per thread) ----
    #pragma unroll
    for (int it = 0; it < 7; it++) {
        int idx = tid + it * 128;           // 0..895
        int ch  = idx / 112;                // 14*8 per channel
        int rem = idx - ch * 112;
        int r   = rem >> 3;
        int e   = rem & 7;
        int col = (e < 3) ? e : (64 + e);   // 0,1,2,67..71
        xs[ch * 1008 + r * 72 + col] = 0.f;
    }

    const float* kpix = g_kernel + (size_t)b * KK * HW + (h0 + row) * 64 + wloc;

    float acc[8][4];
    #pragma unroll
    for (int cc = 0; cc < 8; cc++)
        #pragma unroll
        for (int p = 0; p < 4; p++) acc[cc][p] = 0.f;

    // prefetch kernel tap-row 0 (overlaps halo STS drain)
    float4 kr[7], krn[7];
    #pragma unroll
    for (int j = 0; j < 7; j++)
        kr[j] = *(const float4*)(kpix + (size_t)j * HW);

    __syncthreads();

    #pragma unroll 1
    for (int i = 0; i < 7; i++) {
        // prefetch next tap-row's weights while computing this one
        if (i < 6) {
            #pragma unroll
            for (int j = 0; j < 7; j++)
                krn[j] = *(const float4*)(kpix + (size_t)((i + 1) * 7 + j) * HW);
        }
        const float* xrow = xs + (row + i) * 72 + wloc;
        #pragma unroll
        for (int cc = 0; cc < 8; cc++) {
            const float* rp = xrow + cc * 1008;
            float4 u0 = *(const float4*)(rp);
            float4 u1 = *(const float4*)(rp + 4);
            float2 u2 = *(const float2*)(rp + 8);
            float va[10] = {u0.x,u0.y,u0.z,u0.w, u1.x,u1.y,u1.z,u1.w, u2.x,u2.y};
            float a0 = acc[cc][0], a1 = acc[cc][1], a2 = acc[cc][2], a3 = acc[cc][3];
            #pragma unroll
            for (int j = 0; j < 7; j++) {
                a0 = fmaf(kr[j].x, va[j],     a0);
                a1 = fmaf(kr[j].y, va[j + 1], a1);
                a2 = fmaf(kr[j].z, va[j + 2], a2);
                a3 = fmaf(kr[j].w, va[j + 3], a3);
            }
            acc[cc][0] = a0; acc[cc][1] = a1; acc[cc][2] = a2; acc[cc][3] = a3;
        }
        #pragma unroll
        for (int j = 0; j < 7; j++) kr[j] = krn[j];
    }

    const size_t out_pix = (size_t)(h0 + row) * 64 + wloc;
    #pragma unroll
    for (int cc = 0; cc < 8; cc++) {
        float4 res;
        res.x = acc[cc][0]; res.y = acc[cc][1];
        res.z = acc[cc][2]; res.w = acc[cc][3];
        *(float4*)(out + ((size_t)(b * NC + c0 + cc) << 12) + out_pix) = res;
    }
}

extern "C" void kernel_launch(void* const* d_in, const int* in_sizes, int n_in,
                              void* d_out, int out_size)
{
    const float* x     = (const float*)d_in[0];
    const float* w1    = (const float*)d_in[1];
    const float* b1    = (const float*)d_in[2];
    const float* gamma = (const float*)d_in[3];
    const float* beta  = (const float*)d_in[4];
    const float* mean  = (const float*)d_in[5];
    const float* var   = (const float*)d_in[6];
    const float* w2    = (const float*)d_in[7];
    const float* b2    = (const float*)d_in[8];

    gen_kernel<<<256, 256>>>(x, w1, b1, gamma, beta, mean, var, w2, b2);
    inv_kernel<<<512, 128>>>(x, (float*)d_out);
}